// round 1
// baseline (speedup 1.0000x reference)
#include <cuda_runtime.h>
#include <cuda_bf16.h>

#define N_NODES 40000
#define N_EDGES 640000
#define D 128

// ---- device scratch (allocation-free rule: __device__ globals) ----
__device__ int   g_deg[N_NODES];
__device__ int   g_cur[N_NODES];
__device__ int   g_off[N_NODES + 1];
__device__ int   g_esrc[N_EDGES];
__device__ float g_ew[N_EDGES];
__device__ float g_y[N_NODES * D];     // y = x @ W

// ---------------------------------------------------------------
__global__ void k_zero() {
    int i = blockIdx.x * blockDim.x + threadIdx.x;
    if (i < N_NODES) { g_deg[i] = 0; g_cur[i] = 0; }
}

__global__ void k_count(const int* __restrict__ dst) {
    int e = blockIdx.x * blockDim.x + threadIdx.x;
    if (e < N_EDGES) atomicAdd(&g_deg[dst[e]], 1);
}

// single-block exclusive scan over g_deg -> g_off (40 chunks of 1024)
__global__ void k_scan() {
    __shared__ int warp_sums[32];
    __shared__ int s_carry;
    int tid = threadIdx.x;
    int lane = tid & 31, wid = tid >> 5;
    if (tid == 0) s_carry = 0;
    __syncthreads();
    for (int base = 0; base < N_NODES; base += 1024) {
        int idx = base + tid;
        int v = (idx < N_NODES) ? g_deg[idx] : 0;
        int incl = v;
        #pragma unroll
        for (int o = 1; o < 32; o <<= 1) {
            int t = __shfl_up_sync(0xffffffffu, incl, o);
            if (lane >= o) incl += t;
        }
        if (lane == 31) warp_sums[wid] = incl;
        __syncthreads();
        if (wid == 0) {
            int ws = warp_sums[lane];
            int wincl = ws;
            #pragma unroll
            for (int o = 1; o < 32; o <<= 1) {
                int t = __shfl_up_sync(0xffffffffu, wincl, o);
                if (lane >= o) wincl += t;
            }
            warp_sums[lane] = wincl - ws;  // exclusive warp offset
        }
        __syncthreads();
        int excl = incl - v + warp_sums[wid] + s_carry;
        if (idx < N_NODES) g_off[idx] = excl;
        __syncthreads();                 // everyone has consumed s_carry
        if (tid == 1023) s_carry = excl + v;  // running total
        __syncthreads();
    }
    if (tid == 0) g_off[N_NODES] = s_carry;
}

// scatter edges into CSR-by-dst; store pre-normalized weight
__global__ void k_fill(const int* __restrict__ src, const int* __restrict__ dst,
                       const float* __restrict__ ew) {
    int e = blockIdx.x * blockDim.x + threadIdx.x;
    if (e < N_EDGES) {
        int d = dst[e];
        int p = g_off[d] + atomicAdd(&g_cur[d], 1);
        g_esrc[p] = src[e];
        g_ew[p]   = ew[e] / (float)g_deg[d];  // deg >= 1 for any dst that appears
    }
}

// y = x @ W  (40000x128 @ 128x128), 64-row tiles, 8x4 register micro-tile
__global__ void k_gemm(const float* __restrict__ x, const float* __restrict__ W) {
    extern __shared__ float sm[];
    float* x_s = sm;                 // 64*128
    float* W_s = sm + 64 * D;        // 128*128
    int tid = threadIdx.x;
    int r0 = blockIdx.x * 64;

    const float4* x4 = (const float4*)(x + (size_t)r0 * D);
    float4* xs4 = (float4*)x_s;
    #pragma unroll
    for (int i = 0; i < 8; i++) xs4[i * 256 + tid] = x4[i * 256 + tid];
    const float4* W4 = (const float4*)W;
    float4* Ws4 = (float4*)W_s;
    #pragma unroll
    for (int i = 0; i < 16; i++) Ws4[i * 256 + tid] = W4[i * 256 + tid];
    __syncthreads();

    int tx = tid & 31, ty = tid >> 5;         // tx: 4-col group, ty: 8-row group
    float acc[8][4] = {};
    const float* xrow = x_s + (ty * 8) * D;
    #pragma unroll 4
    for (int k = 0; k < D; k++) {
        float4 wv = *(const float4*)(W_s + k * D + tx * 4);
        #pragma unroll
        for (int ii = 0; ii < 8; ii++) {
            float hv = xrow[ii * D + k];
            acc[ii][0] += hv * wv.x;
            acc[ii][1] += hv * wv.y;
            acc[ii][2] += hv * wv.z;
            acc[ii][3] += hv * wv.w;
        }
    }
    #pragma unroll
    for (int ii = 0; ii < 8; ii++) {
        float4 o = make_float4(acc[ii][0], acc[ii][1], acc[ii][2], acc[ii][3]);
        ((float4*)(g_y + (size_t)(r0 + ty * 8 + ii) * D))[tx] = o;
    }
}

// out[v] = b + sum_{e in CSR[v]} w_e * y[src_e]; one warp per node
__global__ void k_gather(const float* __restrict__ b, float* __restrict__ out) {
    int w = (blockIdx.x * blockDim.x + threadIdx.x) >> 5;
    int lane = threadIdx.x & 31;
    if (w >= N_NODES) return;
    int beg = g_off[w], end = g_off[w + 1];
    float4 acc = ((const float4*)b)[lane];
    const float4* y4 = (const float4*)g_y;

    int i = beg;
    for (; i + 4 <= end; i += 4) {
        int s0 = g_esrc[i], s1 = g_esrc[i + 1], s2 = g_esrc[i + 2], s3 = g_esrc[i + 3];
        float w0 = g_ew[i], w1 = g_ew[i + 1], w2 = g_ew[i + 2], w3 = g_ew[i + 3];
        float4 v0 = y4[(size_t)s0 * 32 + lane];
        float4 v1 = y4[(size_t)s1 * 32 + lane];
        float4 v2 = y4[(size_t)s2 * 32 + lane];
        float4 v3 = y4[(size_t)s3 * 32 + lane];
        acc.x += w0 * v0.x + w1 * v1.x + w2 * v2.x + w3 * v3.x;
        acc.y += w0 * v0.y + w1 * v1.y + w2 * v2.y + w3 * v3.y;
        acc.z += w0 * v0.z + w1 * v1.z + w2 * v2.z + w3 * v3.z;
        acc.w += w0 * v0.w + w1 * v1.w + w2 * v2.w + w3 * v3.w;
    }
    for (; i < end; i++) {
        int s = g_esrc[i];
        float ww = g_ew[i];
        float4 v = y4[(size_t)s * 32 + lane];
        acc.x += ww * v.x; acc.y += ww * v.y; acc.z += ww * v.z; acc.w += ww * v.w;
    }
    ((float4*)out)[(size_t)w * 32 + lane] = acc;
}

// ---------------------------------------------------------------
extern "C" void kernel_launch(void* const* d_in, const int* in_sizes, int n_in,
                              void* d_out, int out_size) {
    const float* x   = (const float*)d_in[0];
    const int*   src = (const int*)  d_in[1];
    const int*   dst = (const int*)  d_in[2];
    const float* ew  = (const float*)d_in[3];
    const float* W   = (const float*)d_in[4];
    const float* b   = (const float*)d_in[5];
    float* out = (float*)d_out;

    k_zero <<<(N_NODES + 255) / 256, 256>>>();
    k_count<<<(N_EDGES + 255) / 256, 256>>>(dst);
    k_scan <<<1, 1024>>>();
    k_fill <<<(N_EDGES + 255) / 256, 256>>>(src, dst, ew);

    const int gemm_smem = (64 * D + D * D) * (int)sizeof(float);  // 96 KB
    cudaFuncSetAttribute(k_gemm, cudaFuncAttributeMaxDynamicSharedMemorySize, gemm_smem);
    k_gemm <<<N_NODES / 64, 256, gemm_smem>>>(x, W);

    k_gather<<<(N_NODES * 32 + 255) / 256, 256>>>(b, out);
}

// round 2
// speedup vs baseline: 1.0867x; 1.0867x over previous
#include <cuda_runtime.h>
#include <cuda_bf16.h>

#define N_NODES 40000
#define N_EDGES 640000
#define D 128

// ---- device scratch (allocation-free rule: __device__ globals) ----
__device__ int    g_deg[N_NODES];
__device__ int    g_off[N_NODES];        // exclusive offsets; after k_fill: end offsets
__device__ float2 g_edge[N_EDGES];       // packed {src_as_float_bits, weight}
__device__ float  g_y[N_NODES * D];      // y = x @ W

// ---------------------------------------------------------------
__global__ void k_count(const int* __restrict__ dst) {
    int e = blockIdx.x * blockDim.x + threadIdx.x;
    if (e < N_EDGES) atomicAdd(&g_deg[dst[e]], 1);
}

// single-block exclusive scan over g_deg -> g_off (40 chunks of 1024)
__global__ void k_scan() {
    __shared__ int warp_sums[32];
    __shared__ int s_carry;
    int tid = threadIdx.x;
    int lane = tid & 31, wid = tid >> 5;
    if (tid == 0) s_carry = 0;
    __syncthreads();
    for (int base = 0; base < N_NODES; base += 1024) {
        int idx = base + tid;
        int v = (idx < N_NODES) ? g_deg[idx] : 0;
        int incl = v;
        #pragma unroll
        for (int o = 1; o < 32; o <<= 1) {
            int t = __shfl_up_sync(0xffffffffu, incl, o);
            if (lane >= o) incl += t;
        }
        if (lane == 31) warp_sums[wid] = incl;
        __syncthreads();
        if (wid == 0) {
            int ws = warp_sums[lane];
            int wincl = ws;
            #pragma unroll
            for (int o = 1; o < 32; o <<= 1) {
                int t = __shfl_up_sync(0xffffffffu, wincl, o);
                if (lane >= o) wincl += t;
            }
            warp_sums[lane] = wincl - ws;  // exclusive warp offset
        }
        __syncthreads();
        int excl = incl - v + warp_sums[wid] + s_carry;
        if (idx < N_NODES) g_off[idx] = excl;
        __syncthreads();                 // everyone has consumed s_carry
        if (tid == 1023) s_carry = excl + v;  // running total
        __syncthreads();
    }
}

// scatter edges into CSR-by-dst; single packed 8B store per edge.
// Bumps g_off[d] directly: afterwards g_off[v] == end(v), beg(v) == g_off[v-1].
__global__ void k_fill(const int* __restrict__ src, const int* __restrict__ dst,
                       const float* __restrict__ ew) {
    int e = blockIdx.x * blockDim.x + threadIdx.x;
    if (e < N_EDGES) {
        int d = dst[e];
        int p = atomicAdd(&g_off[d], 1);
        float w = ew[e] / (float)g_deg[d];   // deg >= 1 for any dst that appears
        g_edge[p] = make_float2(__int_as_float(src[e]), w);
    }
}

// y = x @ W  (40000x128 @ 128x128), 64-row tiles, 8x4 register micro-tile
__global__ void k_gemm(const float* __restrict__ x, const float* __restrict__ W) {
    extern __shared__ float sm[];
    float* x_s = sm;                 // 64*128
    float* W_s = sm + 64 * D;        // 128*128
    int tid = threadIdx.x;
    int r0 = blockIdx.x * 64;

    const float4* x4 = (const float4*)(x + (size_t)r0 * D);
    float4* xs4 = (float4*)x_s;
    #pragma unroll
    for (int i = 0; i < 8; i++) xs4[i * 256 + tid] = x4[i * 256 + tid];
    const float4* W4 = (const float4*)W;
    float4* Ws4 = (float4*)W_s;
    #pragma unroll
    for (int i = 0; i < 16; i++) Ws4[i * 256 + tid] = W4[i * 256 + tid];
    __syncthreads();

    int tx = tid & 31, ty = tid >> 5;         // tx: 4-col group, ty: 8-row group
    float acc[8][4] = {};
    const float* xrow = x_s + (ty * 8) * D;
    #pragma unroll 4
    for (int k = 0; k < D; k++) {
        float4 wv = *(const float4*)(W_s + k * D + tx * 4);
        #pragma unroll
        for (int ii = 0; ii < 8; ii++) {
            float hv = xrow[ii * D + k];
            acc[ii][0] += hv * wv.x;
            acc[ii][1] += hv * wv.y;
            acc[ii][2] += hv * wv.z;
            acc[ii][3] += hv * wv.w;
        }
    }
    #pragma unroll
    for (int ii = 0; ii < 8; ii++) {
        float4 o = make_float4(acc[ii][0], acc[ii][1], acc[ii][2], acc[ii][3]);
        ((float4*)(g_y + (size_t)(r0 + ty * 8 + ii) * D))[tx] = o;
    }
}

// out[v] = b + sum_{e in CSR[v]} w_e * y[src_e]; one warp per node
__global__ void k_gather(const float* __restrict__ b, float* __restrict__ out) {
    int v = (blockIdx.x * blockDim.x + threadIdx.x) >> 5;
    int lane = threadIdx.x & 31;
    if (v >= N_NODES) return;
    int beg = (v == 0) ? 0 : g_off[v - 1];
    int end = g_off[v];
    float4 acc = ((const float4*)b)[lane];
    const float4* y4 = (const float4*)g_y;

    int i = beg;
    for (; i + 4 <= end; i += 4) {
        float2 e0 = g_edge[i],     e1 = g_edge[i + 1];
        float2 e2 = g_edge[i + 2], e3 = g_edge[i + 3];
        int s0 = __float_as_int(e0.x), s1 = __float_as_int(e1.x);
        int s2 = __float_as_int(e2.x), s3 = __float_as_int(e3.x);
        float4 v0 = y4[(size_t)s0 * 32 + lane];
        float4 v1 = y4[(size_t)s1 * 32 + lane];
        float4 v2 = y4[(size_t)s2 * 32 + lane];
        float4 v3 = y4[(size_t)s3 * 32 + lane];
        acc.x += e0.y * v0.x + e1.y * v1.x + e2.y * v2.x + e3.y * v3.x;
        acc.y += e0.y * v0.y + e1.y * v1.y + e2.y * v2.y + e3.y * v3.y;
        acc.z += e0.y * v0.z + e1.y * v1.z + e2.y * v2.z + e3.y * v3.z;
        acc.w += e0.y * v0.w + e1.y * v1.w + e2.y * v2.w + e3.y * v3.w;
    }
    for (; i < end; i++) {
        float2 ee = g_edge[i];
        int s = __float_as_int(ee.x);
        float4 vv = y4[(size_t)s * 32 + lane];
        acc.x += ee.y * vv.x; acc.y += ee.y * vv.y;
        acc.z += ee.y * vv.z; acc.w += ee.y * vv.w;
    }
    ((float4*)out)[(size_t)v * 32 + lane] = acc;
}

// ---------------------------------------------------------------
extern "C" void kernel_launch(void* const* d_in, const int* in_sizes, int n_in,
                              void* d_out, int out_size) {
    const float* x   = (const float*)d_in[0];
    const int*   src = (const int*)  d_in[1];
    const int*   dst = (const int*)  d_in[2];
    const float* ew  = (const float*)d_in[3];
    const float* W   = (const float*)d_in[4];
    const float* b   = (const float*)d_in[5];
    float* out = (float*)d_out;

    // side stream + events for fork/join inside graph capture.
    // kernel_launch is only invoked a couple of times (correctness + capture),
    // so fresh creation per call is cheap and keeps the call deterministic.
    cudaStream_t s1;
    cudaStreamCreateWithFlags(&s1, cudaStreamNonBlocking);
    cudaEvent_t e_fork, e_join;
    cudaEventCreateWithFlags(&e_fork, cudaEventDisableTiming);
    cudaEventCreateWithFlags(&e_join, cudaEventDisableTiming);

    // fork: GEMM branch (independent of CSR build)
    cudaEventRecord(e_fork, 0);
    cudaStreamWaitEvent(s1, e_fork, 0);
    const int gemm_smem = (64 * D + D * D) * (int)sizeof(float);  // 96 KB
    cudaFuncSetAttribute(k_gemm, cudaFuncAttributeMaxDynamicSharedMemorySize, gemm_smem);
    k_gemm<<<N_NODES / 64, 256, gemm_smem, s1>>>(x, W);
    cudaEventRecord(e_join, s1);

    // main branch: CSR build
    void* deg_ptr;
    cudaGetSymbolAddress(&deg_ptr, g_deg);
    cudaMemsetAsync(deg_ptr, 0, N_NODES * sizeof(int), 0);
    k_count<<<(N_EDGES + 255) / 256, 256>>>(dst);
    k_scan <<<1, 1024>>>();
    k_fill <<<(N_EDGES + 255) / 256, 256>>>(src, dst, ew);

    // join, then gather (needs both y and CSR)
    cudaStreamWaitEvent(0, e_join, 0);
    k_gather<<<(N_NODES * 32 + 255) / 256, 256>>>(b, out);
}